// round 12
// baseline (speedup 1.0000x reference)
#include <cuda_runtime.h>
#include <cuda_fp16.h>
#include <math.h>
#include <stdint.h>

// Problem constants
#define HDIM   2880
#define NHEADS 64
#define NKV    8
#define DHEAD  64
#define GRP    8          // NHEADS / NKV
#define WIN    128
#define QKVW   5120       // (NHEADS + 2*NKV) * DHEAD
#define AOW    4096       // NHEADS * DHEAD
#define NMAX   1024

// Scratch (device globals: allocation-free)
__device__ float g_qkv[NMAX * QKVW];   // 20 MB
__device__ int   g_positions[NMAX];

__device__ __align__(16) __half g_ah[NMAX * HDIM];    // fp16 hidden states
__device__ __align__(16) __half g_ath[NMAX * AOW];    // fp16 attn output
__device__ __align__(16) __half g_wq[HDIM * QKVW];    // fp16 Wqkv
__device__ __align__(16) __half g_wo[AOW * HDIM];     // fp16 Wo
__device__ __align__(16) __half g_kb[NMAX * NKV * DHEAD];  // roped K, fp16
__device__ __align__(16) __half g_vb[NMAX * NKV * DHEAD];  // V, fp16

// ---------------------------------------------------------------------------
// positions normalizer (int32 vs int64 robust; positions are arange here)
// ---------------------------------------------------------------------------
__global__ void norm_pos_kernel(const void* __restrict__ pos_raw, int n)
{
    const long long* p64 = (const long long*)pos_raw;
    const int*       p32 = (const int*)pos_raw;
    __shared__ int is64;
    if (threadIdx.x == 0) {
        long long v0 = p64[0];
        long long v1 = (n > 1) ? p64[1] : 1;
        is64 = (v0 == 0 && v1 == 1) ? 1 : 0;
    }
    __syncthreads();
    for (int i = threadIdx.x; i < n; i += blockDim.x)
        g_positions[i] = is64 ? (int)p64[i] : p32[i];
}

// ---------------------------------------------------------------------------
// fused fp32 -> fp16 conversion of hs, Wqkv, Wo (one launch)
// ---------------------------------------------------------------------------
__device__ __forceinline__ void cvt4(const float* __restrict__ s,
                                     __half* __restrict__ d, int i)
{
    float4 v = ((const float4*)s)[i];
    __half2 p0 = __halves2half2(__float2half(v.x), __float2half(v.y));
    __half2 p1 = __halves2half2(__float2half(v.z), __float2half(v.w));
    uint2 o;
    o.x = *(uint32_t*)&p0; o.y = *(uint32_t*)&p1;
    ((uint2*)d)[i] = o;
}

__global__ void cvt_all_kernel(const float* __restrict__ hs,
                               const float* __restrict__ wqkv,
                               const float* __restrict__ wo,
                               __half* __restrict__ ah,
                               __half* __restrict__ wq,
                               __half* __restrict__ wo16,
                               int n4_hs, int n4_wq, int n4_wo)
{
    int i = blockIdx.x * blockDim.x + threadIdx.x;
    if (i < n4_hs) { cvt4(hs, ah, i); return; }
    i -= n4_hs;
    if (i < n4_wq) { cvt4(wqkv, wq, i); return; }
    i -= n4_wq;
    if (i < n4_wo) { cvt4(wo, wo16, i); }
}

// ---------------------------------------------------------------------------
// MMA helpers
// ---------------------------------------------------------------------------
__device__ __forceinline__ uint32_t smem_u32(const void* p) {
    return (uint32_t)__cvta_generic_to_shared(p);
}
__device__ __forceinline__ void ldsm_x4(uint32_t* r, uint32_t addr) {
    asm volatile("ldmatrix.sync.aligned.m8n8.x4.shared.b16 {%0,%1,%2,%3}, [%4];"
        : "=r"(r[0]), "=r"(r[1]), "=r"(r[2]), "=r"(r[3]) : "r"(addr));
}
__device__ __forceinline__ void ldsm_x4_t(uint32_t* r, uint32_t addr) {
    asm volatile("ldmatrix.sync.aligned.m8n8.x4.trans.shared.b16 {%0,%1,%2,%3}, [%4];"
        : "=r"(r[0]), "=r"(r[1]), "=r"(r[2]), "=r"(r[3]) : "r"(addr));
}
__device__ __forceinline__ void mma_fp16(float* d, const uint32_t* a, const uint32_t* b) {
    asm volatile(
        "mma.sync.aligned.m16n8k16.row.col.f32.f16.f16.f32 "
        "{%0,%1,%2,%3}, {%4,%5,%6,%7}, {%8,%9}, {%0,%1,%2,%3};"
        : "+f"(d[0]), "+f"(d[1]), "+f"(d[2]), "+f"(d[3])
        : "r"(a[0]), "r"(a[1]), "r"(a[2]), "r"(a[3]), "r"(b[0]), "r"(b[1]));
}
__device__ __forceinline__ void cp16(uint32_t dst, const void* src) {
    asm volatile("cp.async.cg.shared.global [%0], [%1], 16;"
        :: "r"(dst), "l"(src));
}

// ---------------------------------------------------------------------------
// 1-pass fp16 GEMM, BK=64 stages, NS-stage cp.async pipeline, single barrier
// per k-iteration, 2 CTAs/SM.  C[M,N] = A @ B, fp32 accum.
// Block tile 128 x TN_ x 64; warps 2 x (TN_/32), warp tile 64x32.
// Requires M%128==0, N%TN_==0, K%64==0.
// Pipeline: at iter kt, wait_group NS-2 guarantees tile kt arrived; the
// barrier then proves all warps finished reading slot (kt-1)%NS, which is
// exactly the slot tile kt+NS-1 is issued into.
// ---------------------------------------------------------------------------
extern __shared__ char dsm[];

#define BK 64
#define SKA_H 72   // A smem row stride in halves (144B): conflict-free ldsm

template<int TN_, int NS>
__global__ __launch_bounds__(TN_ * 2, 2) void gemm1p_kernel(
    const __half* __restrict__ A, const __half* __restrict__ B,
    float* __restrict__ C, int M, int N, int K)
{
    constexpr int NT   = TN_ * 2;
    constexpr int SKB_ = TN_ + 8;                       // halves
    constexpr uint32_t OFF_B = 128u * SKA_H * 2u;       // 18432
    constexpr uint32_t STG   = OFF_B + (uint32_t)BK * SKB_ * 2u;
    constexpr int AGRAN = 128 * (BK / 8);               // 1024
    constexpr int BGRAN = BK * (TN_ / 8);

    const int tid  = threadIdx.x;
    const int wid  = tid >> 5;
    const int lane = tid & 31;
    const int m0 = blockIdx.y * 128;
    const int n0 = blockIdx.x * TN_;

    const int wm = (wid & 1) * 64;
    const int wn = (wid >> 1) * 32;

    const uint32_t sb = smem_u32(dsm);

    float acc[4][4][4];
    #pragma unroll
    for (int i = 0; i < 4; i++)
        #pragma unroll
        for (int j = 0; j < 4; j++)
            #pragma unroll
            for (int k = 0; k < 4; k++) acc[i][j][k] = 0.0f;

    const int nk = K / BK;

    auto issue = [&](int slot, int kc) {
        const uint32_t s = sb + (uint32_t)slot * STG;
        for (int i = tid; i < AGRAN; i += NT) {        // A: 128 rows x 8 granules
            int r = i >> 3, c = i & 7;
            uint32_t off = (uint32_t)(r * (SKA_H * 2) + c * 16);
            size_t g = (size_t)(m0 + r) * K + (size_t)kc * BK + c * 8;
            cp16(s + off, A + g);
        }
        for (int i = tid; i < BGRAN; i += NT) {        // B: 64 rows x TN_/8 granules
            int r = i / (TN_ / 8), c = i % (TN_ / 8);
            uint32_t off = (uint32_t)(r * (SKB_ * 2) + c * 16);
            size_t g = (size_t)(kc * BK + r) * N + n0 + c * 8;
            cp16(s + OFF_B + off, B + g);
        }
    };

    // prologue: NS-1 stages committed
    #pragma unroll
    for (int s = 0; s < NS - 1; s++) {
        if (s < nk) issue(s, s);
        asm volatile("cp.async.commit_group;");
    }

    const int lm_row = lane & 15;
    const int lm_kch = (lane >> 4) * 8;

    for (int kt = 0; kt < nk; kt++) {
        asm volatile("cp.async.wait_group %0;" :: "n"(NS - 2));  // tile kt arrived
        __syncthreads();                 // all reads of slot (kt-1)%NS retired

        if (kt + NS - 1 < nk) {
            int ps = (kt + NS - 1) % NS;
            issue(ps, kt + NS - 1);
        }
        asm volatile("cp.async.commit_group;");

        const uint32_t stg = sb + (uint32_t)(kt % NS) * STG;

        #pragma unroll
        for (int ks = 0; ks < BK / 16; ks++) {
            const int k0 = ks * 16;
            uint32_t ah[4][4], bb[2][4];
            #pragma unroll
            for (int mi = 0; mi < 4; mi++) {
                uint32_t off = (uint32_t)((wm + mi * 16 + lm_row) * (SKA_H * 2)
                                          + (k0 + lm_kch) * 2);
                ldsm_x4(ah[mi], stg + off);
            }
            #pragma unroll
            for (int np = 0; np < 2; np++) {
                uint32_t off = (uint32_t)((k0 + lm_row) * (SKB_ * 2)
                                          + (wn + np * 16 + lm_kch) * 2);
                ldsm_x4_t(bb[np], stg + OFF_B + off);
            }
            #pragma unroll
            for (int mi = 0; mi < 4; mi++) {
                #pragma unroll
                for (int nj = 0; nj < 4; nj++) {
                    const uint32_t* bp = &bb[nj >> 1][(nj & 1) * 2];
                    mma_fp16(acc[mi][nj], ah[mi], bp);
                }
            }
        }
    }

    const int er = lane >> 2;
    const int ec = (lane & 3) * 2;
    #pragma unroll
    for (int mi = 0; mi < 4; mi++) {
        #pragma unroll
        for (int nj = 0; nj < 4; nj++) {
            const int row = m0 + wm + mi * 16 + er;
            const int col = n0 + wn + nj * 8 + ec;
            float2 v01; v01.x = acc[mi][nj][0]; v01.y = acc[mi][nj][1];
            float2 v23; v23.x = acc[mi][nj][2]; v23.y = acc[mi][nj][3];
            *(float2*)&C[(size_t)row * N + col]       = v01;
            *(float2*)&C[(size_t)(row + 8) * N + col] = v23;
        }
    }
}

#define SMEM_T64 (4 * (18432 + 64 * 72 * 2))    // 4*27648 = 110592
#define SMEM_T96 (3 * (18432 + 64 * 104 * 2))   // 3*31744 = 95232

// ---------------------------------------------------------------------------
// RoPE + K/V extraction. q roped in place (fp32); k roped -> fp16 g_kb;
// v copied -> fp16 g_vb.  Grid covers n*2304 rope threads + n*256 v-pairs.
// ---------------------------------------------------------------------------
__global__ void rope_kv_kernel(float* __restrict__ qkv,
                               __half* __restrict__ kb,
                               __half* __restrict__ vb, int n)
{
    int idx = blockIdx.x * blockDim.x + threadIdx.x;
    const int nrope = n * (NHEADS + NKV) * (DHEAD / 2);

    if (idx < nrope) {
        int j   = idx & 31;
        int h   = (idx >> 5) % (NHEADS + NKV);
        int tok = idx / ((NHEADS + NKV) * 32);

        float pos = (float)g_positions[tok];
        float inv_freq = powf(150000.0f, -((float)j) / 32.0f);
        float ang = pos * inv_freq;
        float s, c;
        sincosf(ang, &s, &c);

        if (h < NHEADS) {
            float* base = qkv + (size_t)tok * QKVW + h * DHEAD;
            float x1 = base[j];
            float x2 = base[j + 32];
            base[j]      = x1 * c - x2 * s;
            base[j + 32] = x2 * c + x1 * s;
        } else {
            int kh = h - NHEADS;
            const float* base = qkv + (size_t)tok * QKVW + NHEADS * DHEAD
                              + (size_t)kh * DHEAD;
            float x1 = base[j];
            float x2 = base[j + 32];
            __half* kout = kb + ((size_t)tok * NKV + kh) * DHEAD;
            kout[j]      = __float2half(x1 * c - x2 * s);
            kout[j + 32] = __float2half(x2 * c + x1 * s);
        }
        return;
    }

    int iv = idx - nrope;                       // v half2 pairs
    int totv = n * NKV * DHEAD / 2;             // n*256
    if (iv >= totv) return;
    int tok = iv >> 8;
    int r   = (iv & 255) * 2;
    const float* src = qkv + (size_t)tok * QKVW + (NHEADS + NKV) * DHEAD + r;
    __half2 hv = __halves2half2(__float2half(src[0]), __float2half(src[1]));
    *(__half2*)&vb[(size_t)tok * (NKV * DHEAD) + r] = hv;
}

// ---------------------------------------------------------------------------
// Sliding-window attention with sinks, 4 tokens per block, fp16 K/V.
// Grid: (n/4, NKV). Block: 256 threads, dynamic smem ~43 KB (5 CTAs/SM).
// Union window = 131 slots. Output written as fp16.
// ---------------------------------------------------------------------------
#define UNI 131
// smem: kbufh 132*72 halves = 19008 B, qs 2048 f, sc 4224 f, dinv 32 f
#define ATTN_SMEM (19008 + (2048 + 4224 + 32) * 4)   // 44224 B

__global__ __launch_bounds__(256) void attn_kernel(
    const float* __restrict__ qkv, const __half* __restrict__ kb,
    const __half* __restrict__ vb, const float* __restrict__ sinks,
    __half* __restrict__ out16, int n)
{
    __half* kbufh = (__half*)dsm;                 // [132][72] halves (K then V)
    float*  qs    = (float*)(dsm + 19008);        // [4][8][64]
    float*  sc    = qs + 2048;                    // [4][8][132]
    float*  dinv  = sc + 4224;                    // [32]

    const int tok0 = blockIdx.x * 4;
    const int kv   = blockIdx.y;
    const int tid  = threadIdx.x;
    const int lane = tid & 31;
    const int wid  = tid >> 5;

    const int p0 = g_positions[tok0];

    // q for 4 tokens, pre-scaled
    for (int i = tid; i < 4 * GRP * DHEAD; i += 256) {
        int j = i >> 9, r = i & 511;
        qs[((j << 3) + (r >> 6)) * 64 + (r & 63)] =
            qkv[(size_t)(tok0 + j) * QKVW + (size_t)kv * GRP * DHEAD + r] * 0.125f;
    }

    // K union window: 131 rows x 64 halves (8 granules/row)
    for (int i = tid; i < UNI * 8; i += 256) {
        int u  = i >> 3;
        int c8 = (i & 7) << 3;
        int t = p0 - (WIN - 1) + u;
        t = max(0, min(t, n - 1));
        uint4 kd = *(const uint4*)(kb + ((size_t)t * NKV + kv) * DHEAD + c8);
        *(uint4*)&kbufh[u * 72 + c8] = kd;
    }
    __syncthreads();

    // scores
    if (tid < UNI) {
        const int u = tid;
        float s[4][GRP];
        #pragma unroll
        for (int j = 0; j < 4; j++)
            #pragma unroll
            for (int g = 0; g < GRP; g++) s[j][g] = 0.0f;

        #pragma unroll
        for (int d8 = 0; d8 < 8; d8++) {
            uint4 kr = *(const uint4*)&kbufh[u * 72 + d8 * 8];
            float f[8];
            {
                float2 t0 = __half22float2(*(__half2*)&kr.x);
                float2 t1 = __half22float2(*(__half2*)&kr.y);
                float2 t2 = __half22float2(*(__half2*)&kr.z);
                float2 t3 = __half22float2(*(__half2*)&kr.w);
                f[0]=t0.x; f[1]=t0.y; f[2]=t1.x; f[3]=t1.y;
                f[4]=t2.x; f[5]=t2.y; f[6]=t3.x; f[7]=t3.y;
            }
            #pragma unroll
            for (int j = 0; j < 4; j++)
                #pragma unroll
                for (int g = 0; g < GRP; g++) {
                    const float* qp = &qs[((j << 3) + g) * 64 + d8 * 8];
                    float4 q0 = *(const float4*)qp;
                    float4 q1 = *(const float4*)(qp + 4);
                    s[j][g] += f[0]*q0.x + f[1]*q0.y + f[2]*q0.z + f[3]*q0.w
                             + f[4]*q1.x + f[5]*q1.y + f[6]*q1.z + f[7]*q1.w;
                }
        }

        const bool tvalid = (p0 - (WIN - 1) + u) >= 0;
        #pragma unroll
        for (int j = 0; j < 4; j++) {
            int w = u - j;
            bool inw = (w >= 0) && (w < WIN);
            #pragma unroll
            for (int g = 0; g < GRP; g++)
                sc[((j << 3) + g) * 132 + u] =
                    inw ? (tvalid ? s[j][g] : -INFINITY) : 0.0f;
        }
    }
    __syncthreads();

    // softmax: 32 (j,g) pairs, warp wid handles pairs 4*wid .. 4*wid+3
    #pragma unroll
    for (int pp = 0; pp < 4; pp++) {
        int p = (wid << 2) + pp;
        int j = p >> 3, g = p & 7;
        float* base = &sc[p * 132];
        float vals[4];
        #pragma unroll
        for (int i = 0; i < 4; i++)
            vals[i] = base[j + lane + i * 32];
        float m = fmaxf(fmaxf(vals[0], vals[1]), fmaxf(vals[2], vals[3]));
        #pragma unroll
        for (int off = 16; off; off >>= 1)
            m = fmaxf(m, __shfl_xor_sync(0xffffffffu, m, off));
        float snk = sinks[kv * GRP + g];
        m = fmaxf(m, snk);
        float ssum = 0.0f;
        #pragma unroll
        for (int i = 0; i < 4; i++) {
            float pv = expf(vals[i] - m);
            base[j + lane + i * 32] = pv;
            ssum += pv;
        }
        #pragma unroll
        for (int off = 16; off; off >>= 1)
            ssum += __shfl_xor_sync(0xffffffffu, ssum, off);
        if (lane == 0)
            dinv[p] = 1.0f / (ssum + expf(snk - m));
    }

    // V union window into kbufh (reuse)
    for (int i = tid; i < UNI * 8; i += 256) {
        int u  = i >> 3;
        int c8 = (i & 7) << 3;
        int t = p0 - (WIN - 1) + u;
        t = max(0, min(t, n - 1));
        uint4 vd = *(const uint4*)(vb + ((size_t)t * NKV + kv) * DHEAD + c8);
        *(uint4*)&kbufh[u * 72 + c8] = vd;
    }
    __syncthreads();

    // PV: warp wid = head g, lane owns half2 at d2 = lane*2; 4 tokens
    {
        const int g  = wid;
        const int d2 = lane * 2;
        float a[4][2];
        #pragma unroll
        for (int j = 0; j < 4; j++) { a[j][0] = 0.f; a[j][1] = 0.f; }

        #pragma unroll 4
        for (int u = 0; u < UNI; u++) {
            float2 vd = __half22float2(*(__half2*)&kbufh[u * 72 + d2]);
            #pragma unroll
            for (int j = 0; j < 4; j++) {
                float pv = sc[((j << 3) + g) * 132 + u];
                a[j][0] += pv * vd.x;
                a[j][1] += pv * vd.y;
            }
        }

        #pragma unroll
        for (int j = 0; j < 4; j++) {
            float di = dinv[(j << 3) + g];
            size_t o = (size_t)(tok0 + j) * AOW
                     + ((size_t)kv * GRP + g) * DHEAD + d2;
            __half2 hv = __halves2half2(__float2half(a[j][0] * di),
                                        __float2half(a[j][1] * di));
            *(__half2*)&out16[o] = hv;
        }
    }
}

// ---------------------------------------------------------------------------
extern "C" void kernel_launch(void* const* d_in, const int* in_sizes, int n_in,
                              void* d_out, int out_size)
{
    const float* hs    = (const float*)d_in[0];
    const float* wqkv  = (const float*)d_in[1];
    const float* wo    = (const float*)d_in[2];
    const float* sinks = (const float*)d_in[3];
    const void*  pos   = (const void*)d_in[4];
    float*       out   = (float*)d_out;

    const int n = in_sizes[0] / HDIM;   // 1024

    float* qkv_ptr;
    __half *ah, *ath, *wq, *wo16, *kb, *vb;
    cudaGetSymbolAddress((void**)&qkv_ptr, g_qkv);
    cudaGetSymbolAddress((void**)&ah,   g_ah);
    cudaGetSymbolAddress((void**)&ath,  g_ath);
    cudaGetSymbolAddress((void**)&wq,   g_wq);
    cudaGetSymbolAddress((void**)&wo16, g_wo);
    cudaGetSymbolAddress((void**)&kb,   g_kb);
    cudaGetSymbolAddress((void**)&vb,   g_vb);

    cudaFuncSetAttribute((const void*)gemm1p_kernel<64, 4>,
                         cudaFuncAttributeMaxDynamicSharedMemorySize, SMEM_T64);
    cudaFuncSetAttribute((const void*)gemm1p_kernel<96, 3>,
                         cudaFuncAttributeMaxDynamicSharedMemorySize, SMEM_T96);
    cudaFuncSetAttribute((const void*)attn_kernel,
                         cudaFuncAttributeMaxDynamicSharedMemorySize, ATTN_SMEM);

    // 0) normalize positions
    norm_pos_kernel<<<1, 1024>>>(pos, n);

    // 1) fused fp16 conversions
    {
        int n4_hs = (n * HDIM) / 4;
        int n4_wq = (HDIM * QKVW) / 4;
        int n4_wo = (AOW * HDIM) / 4;
        int tot = n4_hs + n4_wq + n4_wo;
        cvt_all_kernel<<<(tot + 255) / 256, 256>>>(hs, wqkv, wo, ah, wq, wo16,
                                                   n4_hs, n4_wq, n4_wo);
    }

    // 2) qkv = hs @ Wqkv   (fp16, BK=64, 4-stage pipeline)
    {
        dim3 grid(QKVW / 64, n / 128);
        gemm1p_kernel<64, 4><<<grid, 128, SMEM_T64>>>(ah, wq, qkv_ptr,
                                                      n, QKVW, HDIM);
    }

    // 3) RoPE q in place; roped K + V to fp16 buffers
    {
        int total = n * (NHEADS + NKV) * (DHEAD / 2) + n * NKV * DHEAD / 2;
        rope_kv_kernel<<<(total + 255) / 256, 256>>>(qkv_ptr, kb, vb, n);
    }

    // 4) attention (4 tokens/block, fp16 K/V), writes fp16 directly
    {
        dim3 grid(n / 4, NKV);
        attn_kernel<<<grid, 256, ATTN_SMEM>>>(qkv_ptr, kb, vb, sinks, ath, n);
    }

    // 5) out = attn @ Wo   (fp16, BK=64, 3-stage, N tile 96 single wave)
    {
        dim3 grid(HDIM / 96, n / 128);
        gemm1p_kernel<96, 3><<<grid, 192, SMEM_T96>>>(ath, wo16, out,
                                                      n, HDIM, AOW);
    }
}

// round 13
// speedup vs baseline: 1.0767x; 1.0767x over previous
#include <cuda_runtime.h>
#include <cuda_fp16.h>
#include <math.h>
#include <stdint.h>

// Problem constants
#define HDIM   2880
#define NHEADS 64
#define NKV    8
#define DHEAD  64
#define GRP    8          // NHEADS / NKV
#define WIN    128
#define QKVW   5120       // (NHEADS + 2*NKV) * DHEAD
#define AOW    4096       // NHEADS * DHEAD
#define NMAX   1024

// Scratch (device globals: allocation-free)
__device__ float g_qkv[NMAX * QKVW];   // 20 MB
__device__ int   g_positions[NMAX];
__device__ float g_cs[NMAX * 32 * 2];  // interleaved cos/sin per (tok, j)

__device__ __align__(16) __half g_ah[NMAX * HDIM];    // fp16 hidden states
__device__ __align__(16) __half g_ath[NMAX * AOW];    // fp16 attn output
__device__ __align__(16) __half g_wq[HDIM * QKVW];    // fp16 Wqkv
__device__ __align__(16) __half g_wo[AOW * HDIM];     // fp16 Wo

// ---------------------------------------------------------------------------
// positions normalizer + RoPE cos/sin table (fused, multi-block).
// Handles int32 vs int64 positions (arange in this problem).
// ---------------------------------------------------------------------------
__global__ void pos_table_kernel(const void* __restrict__ pos_raw, int n)
{
    const long long* p64 = (const long long*)pos_raw;
    const int*       p32 = (const int*)pos_raw;

    __shared__ int is64;
    if (threadIdx.x == 0) {
        long long v0 = p64[0];
        long long v1 = (n > 1) ? p64[1] : 1;
        is64 = (v0 == 0 && v1 == 1) ? 1 : 0;
    }
    __syncthreads();

    int idx = blockIdx.x * blockDim.x + threadIdx.x;
    if (idx >= n * 32) return;

    int tok = idx >> 5;
    int j   = idx & 31;

    int p = is64 ? (int)p64[tok] : p32[tok];
    if (j == 0) g_positions[tok] = p;

    float inv_freq = powf(150000.0f, -((float)j) / 32.0f);
    float s, c;
    sincosf((float)p * inv_freq, &s, &c);
    g_cs[idx * 2]     = c;
    g_cs[idx * 2 + 1] = s;
}

// ---------------------------------------------------------------------------
// fused fp32 -> fp16 conversion of hs, Wqkv, Wo; 4 independent elems/thread.
// ---------------------------------------------------------------------------
__device__ __forceinline__ void cvt4(const float* __restrict__ s,
                                     __half* __restrict__ d, int i)
{
    float4 v = ((const float4*)s)[i];
    __half2 p0 = __halves2half2(__float2half(v.x), __float2half(v.y));
    __half2 p1 = __halves2half2(__float2half(v.z), __float2half(v.w));
    uint2 o;
    o.x = *(uint32_t*)&p0; o.y = *(uint32_t*)&p1;
    ((uint2*)d)[i] = o;
}

__global__ void cvt_all_kernel(const float* __restrict__ hs,
                               const float* __restrict__ wqkv,
                               const float* __restrict__ wo,
                               __half* __restrict__ ah,
                               __half* __restrict__ wq,
                               __half* __restrict__ wo16,
                               int n4_hs, int n4_wq, int n4_wo, int stride)
{
    int base = blockIdx.x * blockDim.x + threadIdx.x;
    int tot = n4_hs + n4_wq + n4_wo;
    #pragma unroll
    for (int q = 0; q < 4; q++) {
        int i = base + q * stride;
        if (i >= tot) break;
        if (i < n4_hs) { cvt4(hs, ah, i); continue; }
        int i2 = i - n4_hs;
        if (i2 < n4_wq) { cvt4(wqkv, wq, i2); continue; }
        cvt4(wo, wo16, i2 - n4_wq);
    }
}

// ---------------------------------------------------------------------------
// MMA helpers
// ---------------------------------------------------------------------------
__device__ __forceinline__ uint32_t smem_u32(const void* p) {
    return (uint32_t)__cvta_generic_to_shared(p);
}
__device__ __forceinline__ void ldsm_x4(uint32_t* r, uint32_t addr) {
    asm volatile("ldmatrix.sync.aligned.m8n8.x4.shared.b16 {%0,%1,%2,%3}, [%4];"
        : "=r"(r[0]), "=r"(r[1]), "=r"(r[2]), "=r"(r[3]) : "r"(addr));
}
__device__ __forceinline__ void ldsm_x4_t(uint32_t* r, uint32_t addr) {
    asm volatile("ldmatrix.sync.aligned.m8n8.x4.trans.shared.b16 {%0,%1,%2,%3}, [%4];"
        : "=r"(r[0]), "=r"(r[1]), "=r"(r[2]), "=r"(r[3]) : "r"(addr));
}
__device__ __forceinline__ void mma_fp16(float* d, const uint32_t* a, const uint32_t* b) {
    asm volatile(
        "mma.sync.aligned.m16n8k16.row.col.f32.f16.f16.f32 "
        "{%0,%1,%2,%3}, {%4,%5,%6,%7}, {%8,%9}, {%0,%1,%2,%3};"
        : "+f"(d[0]), "+f"(d[1]), "+f"(d[2]), "+f"(d[3])
        : "r"(a[0]), "r"(a[1]), "r"(a[2]), "r"(a[3]), "r"(b[0]), "r"(b[1]));
}
__device__ __forceinline__ void cp16(uint32_t dst, const void* src) {
    asm volatile("cp.async.cg.shared.global [%0], [%1], 16;"
        :: "r"(dst), "l"(src));
}

// ---------------------------------------------------------------------------
// 1-pass fp16 GEMM, 3-stage cp.async pipeline, 2 CTAs/SM (R10-proven).
// C[M,N] = A @ B, fp32 accum.  A [M][K], B [K][N] row-major, both fp16.
// Block tile 128 x TN_ x 32; warps 2 x (TN_/32), warp tile 64x32.
// ---------------------------------------------------------------------------
extern __shared__ char dsm[];

template<int TN_>
__global__ __launch_bounds__(TN_ * 2, 2) void gemm1p_kernel(
    const __half* __restrict__ A, const __half* __restrict__ B,
    float* __restrict__ C, int M, int N, int K)
{
    constexpr int NT   = TN_ * 2;
    constexpr int SKB_ = TN_ + 8;
    constexpr uint32_t OFF_B = 10240;                  // A: 128 rows x 80B
    constexpr uint32_t STG   = 10240u + 32u * SKB_ * 2u;
    constexpr int BGRAN = 32 * (TN_ / 8);

    const int tid  = threadIdx.x;
    const int wid  = tid >> 5;
    const int lane = tid & 31;
    const int m0 = blockIdx.y * 128;
    const int n0 = blockIdx.x * TN_;

    const int wm = (wid & 1) * 64;
    const int wn = (wid >> 1) * 32;

    const uint32_t sb = smem_u32(dsm);

    float acc[4][4][4];
    #pragma unroll
    for (int i = 0; i < 4; i++)
        #pragma unroll
        for (int j = 0; j < 4; j++)
            #pragma unroll
            for (int k = 0; k < 4; k++) acc[i][j][k] = 0.0f;

    const int nk = K / 32;

    auto issue = [&](int slot, int kc) {
        const uint32_t s = sb + (uint32_t)slot * STG;
        #pragma unroll 2
        for (int i = tid; i < 512; i += NT) {
            int r = i >> 2, c = i & 3;
            uint32_t off = (uint32_t)(r * 80 + c * 16);
            size_t g = (size_t)(m0 + r) * K + (size_t)kc * 32 + c * 8;
            cp16(s + off, A + g);
        }
        #pragma unroll 2
        for (int i = tid; i < BGRAN; i += NT) {
            int r = i / (TN_ / 8), c = i % (TN_ / 8);
            uint32_t off = (uint32_t)(r * (SKB_ * 2) + c * 16);
            size_t g = (size_t)(kc * 32 + r) * N + n0 + c * 8;
            cp16(s + OFF_B + off, B + g);
        }
    };

    issue(0, 0);
    asm volatile("cp.async.commit_group;");
    if (nk > 1) issue(1, 1);
    asm volatile("cp.async.commit_group;");

    const int lm_row = lane & 15;
    const int lm_kch = (lane >> 4) * 8;

    int slot = 0;
    for (int kt = 0; kt < nk; kt++) {
        if (kt + 2 < nk) {
            int ps = slot + 2; if (ps >= 3) ps -= 3;
            issue(ps, kt + 2);
        }
        asm volatile("cp.async.commit_group;");
        asm volatile("cp.async.wait_group 2;");
        __syncthreads();

        const uint32_t stg = sb + (uint32_t)slot * STG;

        #pragma unroll
        for (int ks = 0; ks < 2; ks++) {
            const int k0 = ks * 16;
            uint32_t ah[4][4], bb[2][4];
            #pragma unroll
            for (int mi = 0; mi < 4; mi++) {
                uint32_t off = (uint32_t)((wm + mi * 16 + lm_row) * 80
                                          + (k0 + lm_kch) * 2);
                ldsm_x4(ah[mi], stg + off);
            }
            #pragma unroll
            for (int np = 0; np < 2; np++) {
                uint32_t off = (uint32_t)((k0 + lm_row) * (SKB_ * 2)
                                          + (wn + np * 16 + lm_kch) * 2);
                ldsm_x4_t(bb[np], stg + OFF_B + off);
            }
            #pragma unroll
            for (int mi = 0; mi < 4; mi++) {
                #pragma unroll
                for (int nj = 0; nj < 4; nj++) {
                    const uint32_t* bp = &bb[nj >> 1][(nj & 1) * 2];
                    mma_fp16(acc[mi][nj], ah[mi], bp);
                }
            }
        }
        __syncthreads();
        slot++; if (slot >= 3) slot = 0;
    }

    const int er = lane >> 2;
    const int ec = (lane & 3) * 2;
    #pragma unroll
    for (int mi = 0; mi < 4; mi++) {
        #pragma unroll
        for (int nj = 0; nj < 4; nj++) {
            const int row = m0 + wm + mi * 16 + er;
            const int col = n0 + wn + nj * 8 + ec;
            float2 v01; v01.x = acc[mi][nj][0]; v01.y = acc[mi][nj][1];
            float2 v23; v23.x = acc[mi][nj][2]; v23.y = acc[mi][nj][3];
            *(float2*)&C[(size_t)row * N + col]       = v01;
            *(float2*)&C[(size_t)(row + 8) * N + col] = v23;
        }
    }
}

#define SMEM_T64 (3 * (10240 + 32 * 72 * 2))    // 44544
#define SMEM_T96 (3 * (10240 + 32 * 104 * 2))   // 50688

// ---------------------------------------------------------------------------
// RoPE in-place on qkv (q: 64 heads, k: 8 heads), cos/sin from table.
// ---------------------------------------------------------------------------
__global__ void rope_kernel(float* __restrict__ qkv, int n)
{
    int idx = blockIdx.x * blockDim.x + threadIdx.x;
    int total = n * (NHEADS + NKV) * (DHEAD / 2);
    if (idx >= total) return;

    int j   = idx & 31;
    int h   = (idx >> 5) % (NHEADS + NKV);
    int tok = idx / ((NHEADS + NKV) * 32);

    float* base;
    if (h < NHEADS)
        base = qkv + (size_t)tok * QKVW + h * DHEAD;
    else
        base = qkv + (size_t)tok * QKVW + NHEADS * DHEAD + (h - NHEADS) * DHEAD;

    float2 cs = *(const float2*)&g_cs[(tok * 32 + j) * 2];

    float x1 = base[j];
    float x2 = base[j + 32];
    base[j]      = x1 * cs.x - x2 * cs.y;
    base[j + 32] = x2 * cs.x + x1 * cs.y;
}

// ---------------------------------------------------------------------------
// Sliding-window attention with sinks, 4 tokens per block, 288 threads.
// Score phase: threads 0..130 -> j in {0,1}, threads 131..261 -> j in {2,3}
// (91% utilization vs 51% with 256 threads). Softmax/PV on warps 0..7.
// Union window = 131 slots. Output written as fp16.
// ---------------------------------------------------------------------------
#define UNI 131
#define ATHR 288
#define ATTN_SMEM ((8976 + 2048 + 4224 + 32) * 4)   // 61120 B

__global__ __launch_bounds__(ATHR) void attn_kernel(
    const float* __restrict__ qkv, const float* __restrict__ sinks,
    __half* __restrict__ out16, int n)
{
    float* kbuf = (float*)dsm;            // [132][68] (K, then V)
    float* qs   = kbuf + 8976;            // [4][8][64] scaled q
    float* sc   = qs + 2048;              // [4][8][132] scores -> probs
    float* dinv = sc + 4224;              // [32]

    const int tok0 = blockIdx.x * 4;
    const int kv   = blockIdx.y;
    const int tid  = threadIdx.x;
    const int lane = tid & 31;
    const int wid  = tid >> 5;

    const int p0 = g_positions[tok0];

    // load q for 4 tokens (4*512 floats), pre-scaled by 1/sqrt(64)
    for (int i = tid; i < 4 * GRP * DHEAD; i += ATHR) {
        int j = i >> 9, r = i & 511;
        qs[((j << 3) + (r >> 6)) * 64 + (r & 63)] =
            qkv[(size_t)(tok0 + j) * QKVW + (size_t)kv * GRP * DHEAD + r] * 0.125f;
    }

    // load K union window (131 rows x 64)
    for (int i = tid; i < UNI * (DHEAD / 4); i += ATHR) {
        int u  = i >> 4;
        int c4 = (i & 15) << 2;
        int t = p0 - (WIN - 1) + u;
        t = max(0, min(t, n - 1));
        float4 kd = *(const float4*)(qkv + (size_t)t * QKVW + NHEADS * DHEAD
                                     + (size_t)kv * DHEAD + c4);
        *(float4*)&kbuf[u * 68 + c4] = kd;
    }
    __syncthreads();

    // scores: 262 active threads; thread handles (u, 2 tokens)
    if (tid < 2 * UNI) {
        const int half = (tid >= UNI) ? 1 : 0;
        const int u  = tid - half * UNI;
        const int j0 = half * 2;

        float s[2][GRP];
        #pragma unroll
        for (int jj = 0; jj < 2; jj++)
            #pragma unroll
            for (int g = 0; g < GRP; g++) s[jj][g] = 0.0f;

        #pragma unroll 4
        for (int d4 = 0; d4 < DHEAD / 4; d4++) {
            float4 kd = *(const float4*)&kbuf[u * 68 + d4 * 4];
            #pragma unroll
            for (int jj = 0; jj < 2; jj++)
                #pragma unroll
                for (int g = 0; g < GRP; g++) {
                    float4 qv = *(const float4*)
                        &qs[(((j0 + jj) << 3) + g) * 64 + d4 * 4];
                    s[jj][g] += kd.x * qv.x + kd.y * qv.y
                              + kd.z * qv.z + kd.w * qv.w;
                }
        }

        const bool tvalid = (p0 - (WIN - 1) + u) >= 0;
        #pragma unroll
        for (int jj = 0; jj < 2; jj++) {
            int j = j0 + jj;
            int w = u - j;
            bool inw = (w >= 0) && (w < WIN);
            #pragma unroll
            for (int g = 0; g < GRP; g++)
                sc[((j << 3) + g) * 132 + u] =
                    inw ? (tvalid ? s[jj][g] : -INFINITY) : 0.0f;
        }
    }
    __syncthreads();

    // softmax: 32 (j,g) pairs, warp wid (<8) handles pairs 4*wid .. 4*wid+3
    if (wid < 8) {
        #pragma unroll
        for (int pp = 0; pp < 4; pp++) {
            int p = (wid << 2) + pp;
            int j = p >> 3, g = p & 7;
            float* base = &sc[p * 132];
            float vals[4];
            #pragma unroll
            for (int i = 0; i < 4; i++)
                vals[i] = base[j + lane + i * 32];
            float m = fmaxf(fmaxf(vals[0], vals[1]), fmaxf(vals[2], vals[3]));
            #pragma unroll
            for (int off = 16; off; off >>= 1)
                m = fmaxf(m, __shfl_xor_sync(0xffffffffu, m, off));
            float snk = sinks[kv * GRP + g];
            m = fmaxf(m, snk);
            float ssum = 0.0f;
            #pragma unroll
            for (int i = 0; i < 4; i++) {
                float pv = expf(vals[i] - m);
                base[j + lane + i * 32] = pv;
                ssum += pv;
            }
            #pragma unroll
            for (int off = 16; off; off >>= 1)
                ssum += __shfl_xor_sync(0xffffffffu, ssum, off);
            if (lane == 0)
                dinv[p] = 1.0f / (ssum + expf(snk - m));
        }
    }

    // load V union window into kbuf (reuse)
    for (int i = tid; i < UNI * (DHEAD / 4); i += ATHR) {
        int u  = i >> 4;
        int c4 = (i & 15) << 2;
        int t = p0 - (WIN - 1) + u;
        t = max(0, min(t, n - 1));
        float4 vd = *(const float4*)(qkv + (size_t)t * QKVW
                                     + (NHEADS + NKV) * DHEAD
                                     + (size_t)kv * DHEAD + c4);
        *(float4*)&kbuf[u * 68 + c4] = vd;
    }
    __syncthreads();

    // PV: warp wid (<8) = head-in-group g, lane owns d-pair; 4 tokens
    if (wid < 8) {
        const int g  = wid;
        const int d2 = lane * 2;
        float a[4][2];
        #pragma unroll
        for (int j = 0; j < 4; j++) { a[j][0] = 0.f; a[j][1] = 0.f; }

        #pragma unroll 4
        for (int u = 0; u < UNI; u++) {
            float2 vd = *(const float2*)&kbuf[u * 68 + d2];
            #pragma unroll
            for (int j = 0; j < 4; j++) {
                float pv = sc[((j << 3) + g) * 132 + u];
                a[j][0] += pv * vd.x;
                a[j][1] += pv * vd.y;
            }
        }

        #pragma unroll
        for (int j = 0; j < 4; j++) {
            float di = dinv[(j << 3) + g];
            size_t o = (size_t)(tok0 + j) * AOW
                     + ((size_t)kv * GRP + g) * DHEAD + d2;
            __half2 hv = __halves2half2(__float2half(a[j][0] * di),
                                        __float2half(a[j][1] * di));
            *(__half2*)&out16[o] = hv;
        }
    }
}

// ---------------------------------------------------------------------------
extern "C" void kernel_launch(void* const* d_in, const int* in_sizes, int n_in,
                              void* d_out, int out_size)
{
    const float* hs    = (const float*)d_in[0];
    const float* wqkv  = (const float*)d_in[1];
    const float* wo    = (const float*)d_in[2];
    const float* sinks = (const float*)d_in[3];
    const void*  pos   = (const void*)d_in[4];
    float*       out   = (float*)d_out;

    const int n = in_sizes[0] / HDIM;   // 1024

    float* qkv_ptr;
    __half *ah, *ath, *wq, *wo16;
    cudaGetSymbolAddress((void**)&qkv_ptr, g_qkv);
    cudaGetSymbolAddress((void**)&ah,   g_ah);
    cudaGetSymbolAddress((void**)&ath,  g_ath);
    cudaGetSymbolAddress((void**)&wq,   g_wq);
    cudaGetSymbolAddress((void**)&wo16, g_wo);

    cudaFuncSetAttribute(gemm1p_kernel<64>,
                         cudaFuncAttributeMaxDynamicSharedMemorySize, SMEM_T64);
    cudaFuncSetAttribute(gemm1p_kernel<96>,
                         cudaFuncAttributeMaxDynamicSharedMemorySize, SMEM_T96);
    cudaFuncSetAttribute(attn_kernel,
                         cudaFuncAttributeMaxDynamicSharedMemorySize, ATTN_SMEM);

    // 0) positions + RoPE cos/sin table
    {
        int tot = n * 32;
        pos_table_kernel<<<(tot + 255) / 256, 256>>>(pos, n);
    }

    // 1) fused fp16 conversions (4 elems/thread for MLP)
    {
        int n4_hs = (n * HDIM) / 4;
        int n4_wq = (HDIM * QKVW) / 4;
        int n4_wo = (AOW * HDIM) / 4;
        int tot = n4_hs + n4_wq + n4_wo;
        int stride = (tot + 3) / 4;
        cvt_all_kernel<<<(stride + 255) / 256, 256>>>(
            hs, wqkv, wo, ah, wq, wo16, n4_hs, n4_wq, n4_wo, stride);
    }

    // 2) qkv = hs @ Wqkv   (fp16 1-pass, N tile 64: 5120 = 80*64)
    {
        dim3 grid(QKVW / 64, n / 128);
        gemm1p_kernel<64><<<grid, 128, SMEM_T64>>>(ah, wq, qkv_ptr,
                                                   n, QKVW, HDIM);
    }

    // 3) RoPE in place (table-driven)
    {
        int total = n * (NHEADS + NKV) * (DHEAD / 2);
        rope_kernel<<<(total + 255) / 256, 256>>>(qkv_ptr, n);
    }

    // 4) attention (4 tokens/block, 288 threads), writes fp16 directly
    {
        dim3 grid(n / 4, NKV);
        attn_kernel<<<grid, ATHR, ATTN_SMEM>>>(qkv_ptr, sinks, ath, n);
    }

    // 5) out = attn @ Wo   (fp16 1-pass, N tile 96: 2880 = 30*96, single wave)
    {
        dim3 grid(HDIM / 96, n / 128);
        gemm1p_kernel<96><<<grid, 192, SMEM_T96>>>(ath, wo16, out,
                                                   n, HDIM, AOW);
    }
}

// round 14
// speedup vs baseline: 1.2258x; 1.1384x over previous
#include <cuda_runtime.h>
#include <cuda_fp16.h>
#include <math.h>
#include <stdint.h>

// Problem constants
#define HDIM   2880
#define NHEADS 64
#define NKV    8
#define DHEAD  64
#define GRP    8          // NHEADS / NKV
#define WIN    128
#define QKVW   5120       // (NHEADS + 2*NKV) * DHEAD
#define AOW    4096       // NHEADS * DHEAD
#define NMAX   1024

// Scratch (device globals: allocation-free)
__device__ float g_qkv[NMAX * QKVW];   // 20 MB
__device__ int   g_positions[NMAX];
__device__ float g_cs[NMAX * 32 * 2];  // interleaved cos/sin per (tok, j)

__device__ __align__(16) __half g_ah[NMAX * HDIM];    // fp16 hidden states
__device__ __align__(16) __half g_ath[NMAX * AOW];    // fp16 attn output
__device__ __align__(16) __half g_wq[HDIM * QKVW];    // fp16 Wqkv
__device__ __align__(16) __half g_wo[AOW * HDIM];     // fp16 Wo

// ---------------------------------------------------------------------------
// positions normalizer + RoPE cos/sin table (fused, multi-block).
// ---------------------------------------------------------------------------
__global__ void pos_table_kernel(const void* __restrict__ pos_raw, int n)
{
    const long long* p64 = (const long long*)pos_raw;
    const int*       p32 = (const int*)pos_raw;

    __shared__ int is64;
    if (threadIdx.x == 0) {
        long long v0 = p64[0];
        long long v1 = (n > 1) ? p64[1] : 1;
        is64 = (v0 == 0 && v1 == 1) ? 1 : 0;
    }
    __syncthreads();

    int idx = blockIdx.x * blockDim.x + threadIdx.x;
    if (idx >= n * 32) return;

    int tok = idx >> 5;
    int j   = idx & 31;

    int p = is64 ? (int)p64[tok] : p32[tok];
    if (j == 0) g_positions[tok] = p;

    float inv_freq = powf(150000.0f, -((float)j) / 32.0f);
    float s, c;
    sincosf((float)p * inv_freq, &s, &c);
    g_cs[idx * 2]     = c;
    g_cs[idx * 2 + 1] = s;
}

// ---------------------------------------------------------------------------
// fused fp32 -> fp16 conversion of hs, Wqkv, Wo; 4 independent elems/thread.
// ---------------------------------------------------------------------------
__device__ __forceinline__ void cvt4(const float* __restrict__ s,
                                     __half* __restrict__ d, int i)
{
    float4 v = ((const float4*)s)[i];
    __half2 p0 = __halves2half2(__float2half(v.x), __float2half(v.y));
    __half2 p1 = __halves2half2(__float2half(v.z), __float2half(v.w));
    uint2 o;
    o.x = *(uint32_t*)&p0; o.y = *(uint32_t*)&p1;
    ((uint2*)d)[i] = o;
}

__global__ void cvt_all_kernel(const float* __restrict__ hs,
                               const float* __restrict__ wqkv,
                               const float* __restrict__ wo,
                               __half* __restrict__ ah,
                               __half* __restrict__ wq,
                               __half* __restrict__ wo16,
                               int n4_hs, int n4_wq, int n4_wo, int stride)
{
    int base = blockIdx.x * blockDim.x + threadIdx.x;
    int tot = n4_hs + n4_wq + n4_wo;
    #pragma unroll
    for (int q = 0; q < 4; q++) {
        int i = base + q * stride;
        if (i >= tot) break;
        if (i < n4_hs) { cvt4(hs, ah, i); continue; }
        int i2 = i - n4_hs;
        if (i2 < n4_wq) { cvt4(wqkv, wq, i2); continue; }
        cvt4(wo, wo16, i2 - n4_wq);
    }
}

// ---------------------------------------------------------------------------
// MMA helpers
// ---------------------------------------------------------------------------
__device__ __forceinline__ uint32_t smem_u32(const void* p) {
    return (uint32_t)__cvta_generic_to_shared(p);
}
__device__ __forceinline__ void ldsm_x4(uint32_t* r, uint32_t addr) {
    asm volatile("ldmatrix.sync.aligned.m8n8.x4.shared.b16 {%0,%1,%2,%3}, [%4];"
        : "=r"(r[0]), "=r"(r[1]), "=r"(r[2]), "=r"(r[3]) : "r"(addr));
}
__device__ __forceinline__ void ldsm_x4_t(uint32_t* r, uint32_t addr) {
    asm volatile("ldmatrix.sync.aligned.m8n8.x4.trans.shared.b16 {%0,%1,%2,%3}, [%4];"
        : "=r"(r[0]), "=r"(r[1]), "=r"(r[2]), "=r"(r[3]) : "r"(addr));
}
__device__ __forceinline__ void mma_fp16(float* d, const uint32_t* a, const uint32_t* b) {
    asm volatile(
        "mma.sync.aligned.m16n8k16.row.col.f32.f16.f16.f32 "
        "{%0,%1,%2,%3}, {%4,%5,%6,%7}, {%8,%9}, {%0,%1,%2,%3};"
        : "+f"(d[0]), "+f"(d[1]), "+f"(d[2]), "+f"(d[3])
        : "r"(a[0]), "r"(a[1]), "r"(a[2]), "r"(a[3]), "r"(b[0]), "r"(b[1]));
}
__device__ __forceinline__ void cp16(uint32_t dst, const void* src) {
    asm volatile("cp.async.cg.shared.global [%0], [%1], 16;"
        :: "r"(dst), "l"(src));
}

// ---------------------------------------------------------------------------
// 1-pass fp16 GEMM, 3-stage cp.async pipeline, 2 CTAs/SM (R10-proven).
// ---------------------------------------------------------------------------
extern __shared__ char dsm[];

template<int TN_>
__global__ __launch_bounds__(TN_ * 2, 2) void gemm1p_kernel(
    const __half* __restrict__ A, const __half* __restrict__ B,
    float* __restrict__ C, int M, int N, int K)
{
    constexpr int NT   = TN_ * 2;
    constexpr int SKB_ = TN_ + 8;
    constexpr uint32_t OFF_B = 10240;                  // A: 128 rows x 80B
    constexpr uint32_t STG   = 10240u + 32u * SKB_ * 2u;
    constexpr int BGRAN = 32 * (TN_ / 8);

    const int tid  = threadIdx.x;
    const int wid  = tid >> 5;
    const int lane = tid & 31;
    const int m0 = blockIdx.y * 128;
    const int n0 = blockIdx.x * TN_;

    const int wm = (wid & 1) * 64;
    const int wn = (wid >> 1) * 32;

    const uint32_t sb = smem_u32(dsm);

    float acc[4][4][4];
    #pragma unroll
    for (int i = 0; i < 4; i++)
        #pragma unroll
        for (int j = 0; j < 4; j++)
            #pragma unroll
            for (int k = 0; k < 4; k++) acc[i][j][k] = 0.0f;

    const int nk = K / 32;

    auto issue = [&](int slot, int kc) {
        const uint32_t s = sb + (uint32_t)slot * STG;
        #pragma unroll 2
        for (int i = tid; i < 512; i += NT) {
            int r = i >> 2, c = i & 3;
            uint32_t off = (uint32_t)(r * 80 + c * 16);
            size_t g = (size_t)(m0 + r) * K + (size_t)kc * 32 + c * 8;
            cp16(s + off, A + g);
        }
        #pragma unroll 2
        for (int i = tid; i < BGRAN; i += NT) {
            int r = i / (TN_ / 8), c = i % (TN_ / 8);
            uint32_t off = (uint32_t)(r * (SKB_ * 2) + c * 16);
            size_t g = (size_t)(kc * 32 + r) * N + n0 + c * 8;
            cp16(s + OFF_B + off, B + g);
        }
    };

    issue(0, 0);
    asm volatile("cp.async.commit_group;");
    if (nk > 1) issue(1, 1);
    asm volatile("cp.async.commit_group;");

    const int lm_row = lane & 15;
    const int lm_kch = (lane >> 4) * 8;

    int slot = 0;
    for (int kt = 0; kt < nk; kt++) {
        if (kt + 2 < nk) {
            int ps = slot + 2; if (ps >= 3) ps -= 3;
            issue(ps, kt + 2);
        }
        asm volatile("cp.async.commit_group;");
        asm volatile("cp.async.wait_group 2;");
        __syncthreads();

        const uint32_t stg = sb + (uint32_t)slot * STG;

        #pragma unroll
        for (int ks = 0; ks < 2; ks++) {
            const int k0 = ks * 16;
            uint32_t ah[4][4], bb[2][4];
            #pragma unroll
            for (int mi = 0; mi < 4; mi++) {
                uint32_t off = (uint32_t)((wm + mi * 16 + lm_row) * 80
                                          + (k0 + lm_kch) * 2);
                ldsm_x4(ah[mi], stg + off);
            }
            #pragma unroll
            for (int np = 0; np < 2; np++) {
                uint32_t off = (uint32_t)((k0 + lm_row) * (SKB_ * 2)
                                          + (wn + np * 16 + lm_kch) * 2);
                ldsm_x4_t(bb[np], stg + OFF_B + off);
            }
            #pragma unroll
            for (int mi = 0; mi < 4; mi++) {
                #pragma unroll
                for (int nj = 0; nj < 4; nj++) {
                    const uint32_t* bp = &bb[nj >> 1][(nj & 1) * 2];
                    mma_fp16(acc[mi][nj], ah[mi], bp);
                }
            }
        }
        __syncthreads();
        slot++; if (slot >= 3) slot = 0;
    }

    const int er = lane >> 2;
    const int ec = (lane & 3) * 2;
    #pragma unroll
    for (int mi = 0; mi < 4; mi++) {
        #pragma unroll
        for (int nj = 0; nj < 4; nj++) {
            const int row = m0 + wm + mi * 16 + er;
            const int col = n0 + wn + nj * 8 + ec;
            float2 v01; v01.x = acc[mi][nj][0]; v01.y = acc[mi][nj][1];
            float2 v23; v23.x = acc[mi][nj][2]; v23.y = acc[mi][nj][3];
            *(float2*)&C[(size_t)row * N + col]       = v01;
            *(float2*)&C[(size_t)(row + 8) * N + col] = v23;
        }
    }
}

#define SMEM_T64 (3 * (10240 + 32 * 72 * 2))    // 44544
#define SMEM_T96 (3 * (10240 + 32 * 104 * 2))   // 50688

// ---------------------------------------------------------------------------
// RoPE in-place on qkv, cos/sin from table.
// ---------------------------------------------------------------------------
__global__ void rope_kernel(float* __restrict__ qkv, int n)
{
    int idx = blockIdx.x * blockDim.x + threadIdx.x;
    int total = n * (NHEADS + NKV) * (DHEAD / 2);
    if (idx >= total) return;

    int j   = idx & 31;
    int h   = (idx >> 5) % (NHEADS + NKV);
    int tok = idx / ((NHEADS + NKV) * 32);

    float* base;
    if (h < NHEADS)
        base = qkv + (size_t)tok * QKVW + h * DHEAD;
    else
        base = qkv + (size_t)tok * QKVW + NHEADS * DHEAD + (h - NHEADS) * DHEAD;

    float2 cs = *(const float2*)&g_cs[(tok * 32 + j) * 2];

    float x1 = base[j];
    float x2 = base[j + 32];
    base[j]      = x1 * cs.x - x2 * cs.y;
    base[j + 32] = x2 * cs.x + x1 * cs.y;
}

// ---------------------------------------------------------------------------
// HMMA sliding-window attention with sinks, 4 tokens per block.
// Grid: (n/4, NKV). Block: 256 threads (8 warps).
//   p = j*8 + g  (j = token in block 0..3, g = head-in-group 0..7), 32 total.
//   Score:  S[144][32] = Kh[144][64] @ Qd^T   (HMMA, fp16 in, fp32 out)
//   Softmax over window (u = j..j+127) with sinks -> Ps[32][144] fp16 probs
//   PV:     O[32][64]  = Ps[32][144] @ Vh[144][64]
// smem layout (bytes):
//   [0,     20736)  Kh [144][72] halves,  later aliased by S [144][36] floats
//   [20736, 25856)  Qd [64][40] halves   (B operand [d][p])
//   [25856, 35584)  Ps [32][152] halves  (A operand [p][u], zero-padded)
//   [35584, 56320)  Vh [144][72] halves
//   [56320, 56448)  dinv [32] floats
// ---------------------------------------------------------------------------
#define UNI 131
#define ATTN_SMEM 56448

__global__ __launch_bounds__(256) void attn_kernel(
    const float* __restrict__ qkv, const float* __restrict__ sinks,
    __half* __restrict__ out16, int n)
{
    __half* Kh  = (__half*)dsm;               // [144][72]
    float*  S   = (float*)dsm;                // [144][36] (aliases Kh)
    __half* Qd  = (__half*)(dsm + 20736);     // [64][40]
    __half* Ps  = (__half*)(dsm + 25856);     // [32][152]
    __half* Vh  = (__half*)(dsm + 35584);     // [144][72]
    float*  dinv = (float*)(dsm + 56320);     // [32]

    const int tok0 = blockIdx.x * 4;
    const int kv   = blockIdx.y;
    const int tid  = threadIdx.x;
    const int lane = tid & 31;
    const int wid  = tid >> 5;

    const int p0 = g_positions[tok0];

    // --- load Q (scaled, fp16, transposed to [d][p]) ---
    for (int i = tid; i < 32 * 64; i += 256) {
        int p = i >> 6, d = i & 63;
        float v = qkv[(size_t)(tok0 + (p >> 3)) * QKVW
                      + ((size_t)kv * 8 + (p & 7)) * DHEAD + d] * 0.125f;
        Qd[d * 40 + p] = __float2half(v);
    }
    // --- load K, V (fp16), zero pad rows 131..143 ---
    for (int i = tid; i < 144 * 64; i += 256) {
        int u = i >> 6, d = i & 63;
        if (u < UNI) {
            int t = p0 - (WIN - 1) + u;
            t = max(0, min(t, n - 1));
            const float* kvbase = qkv + (size_t)t * QKVW + NHEADS * DHEAD
                                + (size_t)kv * DHEAD + d;
            Kh[u * 72 + d] = __float2half(kvbase[0]);
            Vh[u * 72 + d] = __float2half(kvbase[NKV * DHEAD]);
        } else {
            Kh[u * 72 + d] = __float2half(0.0f);
            Vh[u * 72 + d] = __float2half(0.0f);
        }
    }
    __syncthreads();

    const int lm_row = lane & 15;
    const int lm_kch = (lane >> 4) * 8;
    const int er = lane >> 2;
    const int ec = (lane & 3) * 2;

    const uint32_t khb = smem_u32(Kh);
    const uint32_t qdb = smem_u32(Qd);

    // --- score MMAs: warp w handles m-tile w; warp 0 also m-tile 8 ---
    float sacc[2][4][4];
    #pragma unroll
    for (int z = 0; z < 2; z++)
        #pragma unroll
        for (int nj = 0; nj < 4; nj++)
            #pragma unroll
            for (int q = 0; q < 4; q++) sacc[z][nj][q] = 0.0f;

    const int nmt = (wid == 0) ? 2 : 1;
    for (int z = 0; z < nmt; z++) {
        const int mt = (z == 0) ? wid : 8;
        #pragma unroll
        for (int kk = 0; kk < 4; kk++) {
            uint32_t a[4], bb[2][4];
            ldsm_x4(a, khb + (uint32_t)((mt * 16 + lm_row) * 72
                                        + kk * 16 + lm_kch) * 2);
            #pragma unroll
            for (int np = 0; np < 2; np++)
                ldsm_x4_t(bb[np], qdb + (uint32_t)((kk * 16 + lm_row) * 40
                                                   + np * 16 + lm_kch) * 2);
            #pragma unroll
            for (int nj = 0; nj < 4; nj++)
                mma_fp16(sacc[z][nj], a, &bb[nj >> 1][(nj & 1) * 2]);
        }
    }
    __syncthreads();   // all warps done reading Kh before S overwrites it

    // --- store S fragments; zero Ps ---
    for (int z = 0; z < nmt; z++) {
        const int mt = (z == 0) ? wid : 8;
        #pragma unroll
        for (int nj = 0; nj < 4; nj++) {
            int u0 = mt * 16 + er;
            int c  = nj * 8 + ec;
            float2 v01; v01.x = sacc[z][nj][0]; v01.y = sacc[z][nj][1];
            float2 v23; v23.x = sacc[z][nj][2]; v23.y = sacc[z][nj][3];
            *(float2*)&S[u0 * 36 + c]       = v01;
            *(float2*)&S[(u0 + 8) * 36 + c] = v23;
        }
    }
    for (int i = tid; i < 32 * 152 / 2; i += 256)
        ((uint32_t*)Ps)[i] = 0;
    __syncthreads();

    // --- softmax with sinks: warp wid handles pairs p = 4*wid .. 4*wid+3 ---
    #pragma unroll
    for (int pp = 0; pp < 4; pp++) {
        int p = (wid << 2) + pp;
        int j = p >> 3, g = p & 7;
        float vals[4];
        #pragma unroll
        for (int i = 0; i < 4; i++) {
            int u = j + lane + i * 32;
            bool tvalid = (p0 - (WIN - 1) + u) >= 0;
            vals[i] = tvalid ? S[u * 36 + p] : -INFINITY;
        }
        float m = fmaxf(fmaxf(vals[0], vals[1]), fmaxf(vals[2], vals[3]));
        #pragma unroll
        for (int off = 16; off; off >>= 1)
            m = fmaxf(m, __shfl_xor_sync(0xffffffffu, m, off));
        float snk = sinks[kv * GRP + g];
        m = fmaxf(m, snk);
        float ssum = 0.0f;
        #pragma unroll
        for (int i = 0; i < 4; i++) {
            int u = j + lane + i * 32;
            float pv = expf(vals[i] - m);
            Ps[p * 152 + u] = __float2half(pv);
            ssum += pv;
        }
        #pragma unroll
        for (int off = 16; off; off >>= 1)
            ssum += __shfl_xor_sync(0xffffffffu, ssum, off);
        if (lane == 0)
            dinv[p] = 1.0f / (ssum + expf(snk - m));
    }
    __syncthreads();

    // --- PV MMAs: warp w -> m-tile (w&1), d cols (w>>1)*16 .. +15 ---
    const uint32_t psb = smem_u32(Ps);
    const uint32_t vhb = smem_u32(Vh);
    const int mi = wid & 1;
    const int wn = (wid >> 1) * 16;

    float oacc[2][4];
    #pragma unroll
    for (int nj = 0; nj < 2; nj++)
        #pragma unroll
        for (int q = 0; q < 4; q++) oacc[nj][q] = 0.0f;

    #pragma unroll
    for (int kk = 0; kk < 9; kk++) {
        uint32_t a[4], bb[4];
        ldsm_x4(a, psb + (uint32_t)((mi * 16 + lm_row) * 152
                                    + kk * 16 + lm_kch) * 2);
        ldsm_x4_t(bb, vhb + (uint32_t)((kk * 16 + lm_row) * 72
                                       + wn + lm_kch) * 2);
        mma_fp16(oacc[0], a, &bb[0]);
        mma_fp16(oacc[1], a, &bb[2]);
    }

    // --- epilogue: scale by dinv, write fp16 output ---
    {
        const int pr0 = mi * 16 + er;
        const int pr1 = pr0 + 8;
        const float di0 = dinv[pr0];
        const float di1 = dinv[pr1];
        #pragma unroll
        for (int nj = 0; nj < 2; nj++) {
            const int d = wn + nj * 8 + ec;
            size_t o0 = (size_t)(tok0 + (pr0 >> 3)) * AOW
                      + ((size_t)kv * 8 + (pr0 & 7)) * DHEAD + d;
            size_t o1 = (size_t)(tok0 + (pr1 >> 3)) * AOW
                      + ((size_t)kv * 8 + (pr1 & 7)) * DHEAD + d;
            *(__half2*)&out16[o0] =
                __halves2half2(__float2half(oacc[nj][0] * di0),
                               __float2half(oacc[nj][1] * di0));
            *(__half2*)&out16[o1] =
                __halves2half2(__float2half(oacc[nj][2] * di1),
                               __float2half(oacc[nj][3] * di1));
        }
    }
}

// ---------------------------------------------------------------------------
extern "C" void kernel_launch(void* const* d_in, const int* in_sizes, int n_in,
                              void* d_out, int out_size)
{
    const float* hs    = (const float*)d_in[0];
    const float* wqkv  = (const float*)d_in[1];
    const float* wo    = (const float*)d_in[2];
    const float* sinks = (const float*)d_in[3];
    const void*  pos   = (const void*)d_in[4];
    float*       out   = (float*)d_out;

    const int n = in_sizes[0] / HDIM;   // 1024

    float* qkv_ptr;
    __half *ah, *ath, *wq, *wo16;
    cudaGetSymbolAddress((void**)&qkv_ptr, g_qkv);
    cudaGetSymbolAddress((void**)&ah,   g_ah);
    cudaGetSymbolAddress((void**)&ath,  g_ath);
    cudaGetSymbolAddress((void**)&wq,   g_wq);
    cudaGetSymbolAddress((void**)&wo16, g_wo);

    cudaFuncSetAttribute(gemm1p_kernel<64>,
                         cudaFuncAttributeMaxDynamicSharedMemorySize, SMEM_T64);
    cudaFuncSetAttribute(gemm1p_kernel<96>,
                         cudaFuncAttributeMaxDynamicSharedMemorySize, SMEM_T96);
    cudaFuncSetAttribute(attn_kernel,
                         cudaFuncAttributeMaxDynamicSharedMemorySize, ATTN_SMEM);

    // 0) positions + RoPE cos/sin table
    {
        int tot = n * 32;
        pos_table_kernel<<<(tot + 255) / 256, 256>>>(pos, n);
    }

    // 1) fused fp16 conversions
    {
        int n4_hs = (n * HDIM) / 4;
        int n4_wq = (HDIM * QKVW) / 4;
        int n4_wo = (AOW * HDIM) / 4;
        int tot = n4_hs + n4_wq + n4_wo;
        int stride = (tot + 3) / 4;
        cvt_all_kernel<<<(stride + 255) / 256, 256>>>(
            hs, wqkv, wo, ah, wq, wo16, n4_hs, n4_wq, n4_wo, stride);
    }

    // 2) qkv = hs @ Wqkv   (fp16 1-pass, N tile 64)
    {
        dim3 grid(QKVW / 64, n / 128);
        gemm1p_kernel<64><<<grid, 128, SMEM_T64>>>(ah, wq, qkv_ptr,
                                                   n, QKVW, HDIM);
    }

    // 3) RoPE in place (table-driven)
    {
        int total = n * (NHEADS + NKV) * (DHEAD / 2);
        rope_kernel<<<(total + 255) / 256, 256>>>(qkv_ptr, n);
    }

    // 4) HMMA attention (4 tokens/block), writes fp16 directly
    {
        dim3 grid(n / 4, NKV);
        attn_kernel<<<grid, 256, ATTN_SMEM>>>(qkv_ptr, sinks, ath, n);
    }

    // 5) out = attn @ Wo   (fp16 1-pass, N tile 96, single wave)
    {
        dim3 grid(HDIM / 96, n / 128);
        gemm1p_kernel<96><<<grid, 192, SMEM_T96>>>(ath, wo16, out,
                                                   n, HDIM, AOW);
    }
}

// round 15
// speedup vs baseline: 1.2259x; 1.0001x over previous
#include <cuda_runtime.h>
#include <cuda_fp16.h>
#include <math.h>
#include <stdint.h>

// Problem constants
#define HDIM   2880
#define NHEADS 64
#define NKV    8
#define DHEAD  64
#define GRP    8          // NHEADS / NKV
#define WIN    128
#define QKVW   5120       // (NHEADS + 2*NKV) * DHEAD
#define AOW    4096       // NHEADS * DHEAD
#define NMAX   1024

// Scratch (device globals: allocation-free)
__device__ float g_qkv[NMAX * QKVW];   // 20 MB
__device__ int   g_positions[NMAX];
__device__ float g_cs[NMAX * 32 * 2];  // interleaved cos/sin per (tok, j)

__device__ __align__(16) __half g_ah[NMAX * HDIM];    // fp16 hidden states
__device__ __align__(16) __half g_ath[NMAX * AOW];    // fp16 attn output
__device__ __align__(16) __half g_wq[HDIM * QKVW];    // fp16 Wqkv
__device__ __align__(16) __half g_wo[AOW * HDIM];     // fp16 Wo
__device__ __align__(16) __half g_qb[NMAX * AOW];           // roped+scaled Q fp16
__device__ __align__(16) __half g_kb[NMAX * NKV * DHEAD];   // roped K fp16 (1 MB)
__device__ __align__(16) __half g_vb[NMAX * NKV * DHEAD];   // V fp16 (1 MB)

// ---------------------------------------------------------------------------
// positions normalizer + RoPE cos/sin table (fused, multi-block).
// ---------------------------------------------------------------------------
__global__ void pos_table_kernel(const void* __restrict__ pos_raw, int n)
{
    const long long* p64 = (const long long*)pos_raw;
    const int*       p32 = (const int*)pos_raw;

    __shared__ int is64;
    if (threadIdx.x == 0) {
        long long v0 = p64[0];
        long long v1 = (n > 1) ? p64[1] : 1;
        is64 = (v0 == 0 && v1 == 1) ? 1 : 0;
    }
    __syncthreads();

    int idx = blockIdx.x * blockDim.x + threadIdx.x;
    if (idx >= n * 32) return;

    int tok = idx >> 5;
    int j   = idx & 31;

    int p = is64 ? (int)p64[tok] : p32[tok];
    if (j == 0) g_positions[tok] = p;

    float inv_freq = powf(150000.0f, -((float)j) / 32.0f);
    float s, c;
    sincosf((float)p * inv_freq, &s, &c);
    g_cs[idx * 2]     = c;
    g_cs[idx * 2 + 1] = s;
}

// ---------------------------------------------------------------------------
// fused fp32 -> fp16 conversion of hs, Wqkv, Wo; 4 independent elems/thread.
// ---------------------------------------------------------------------------
__device__ __forceinline__ void cvt4(const float* __restrict__ s,
                                     __half* __restrict__ d, int i)
{
    float4 v = ((const float4*)s)[i];
    __half2 p0 = __halves2half2(__float2half(v.x), __float2half(v.y));
    __half2 p1 = __halves2half2(__float2half(v.z), __float2half(v.w));
    uint2 o;
    o.x = *(uint32_t*)&p0; o.y = *(uint32_t*)&p1;
    ((uint2*)d)[i] = o;
}

__global__ void cvt_all_kernel(const float* __restrict__ hs,
                               const float* __restrict__ wqkv,
                               const float* __restrict__ wo,
                               __half* __restrict__ ah,
                               __half* __restrict__ wq,
                               __half* __restrict__ wo16,
                               int n4_hs, int n4_wq, int n4_wo, int stride)
{
    int base = blockIdx.x * blockDim.x + threadIdx.x;
    int tot = n4_hs + n4_wq + n4_wo;
    #pragma unroll
    for (int q = 0; q < 4; q++) {
        int i = base + q * stride;
        if (i >= tot) break;
        if (i < n4_hs) { cvt4(hs, ah, i); continue; }
        int i2 = i - n4_hs;
        if (i2 < n4_wq) { cvt4(wqkv, wq, i2); continue; }
        cvt4(wo, wo16, i2 - n4_wq);
    }
}

// ---------------------------------------------------------------------------
// MMA helpers
// ---------------------------------------------------------------------------
__device__ __forceinline__ uint32_t smem_u32(const void* p) {
    return (uint32_t)__cvta_generic_to_shared(p);
}
__device__ __forceinline__ void ldsm_x4(uint32_t* r, uint32_t addr) {
    asm volatile("ldmatrix.sync.aligned.m8n8.x4.shared.b16 {%0,%1,%2,%3}, [%4];"
        : "=r"(r[0]), "=r"(r[1]), "=r"(r[2]), "=r"(r[3]) : "r"(addr));
}
__device__ __forceinline__ void ldsm_x4_t(uint32_t* r, uint32_t addr) {
    asm volatile("ldmatrix.sync.aligned.m8n8.x4.trans.shared.b16 {%0,%1,%2,%3}, [%4];"
        : "=r"(r[0]), "=r"(r[1]), "=r"(r[2]), "=r"(r[3]) : "r"(addr));
}
__device__ __forceinline__ void mma_fp16(float* d, const uint32_t* a, const uint32_t* b) {
    asm volatile(
        "mma.sync.aligned.m16n8k16.row.col.f32.f16.f16.f32 "
        "{%0,%1,%2,%3}, {%4,%5,%6,%7}, {%8,%9}, {%0,%1,%2,%3};"
        : "+f"(d[0]), "+f"(d[1]), "+f"(d[2]), "+f"(d[3])
        : "r"(a[0]), "r"(a[1]), "r"(a[2]), "r"(a[3]), "r"(b[0]), "r"(b[1]));
}
__device__ __forceinline__ void cp16(uint32_t dst, const void* src) {
    asm volatile("cp.async.cg.shared.global [%0], [%1], 16;"
        :: "r"(dst), "l"(src));
}

// ---------------------------------------------------------------------------
// 1-pass fp16 GEMM, 3-stage cp.async pipeline, 2 CTAs/SM (R10-proven).
// ---------------------------------------------------------------------------
extern __shared__ char dsm[];

template<int TN_>
__global__ __launch_bounds__(TN_ * 2, 2) void gemm1p_kernel(
    const __half* __restrict__ A, const __half* __restrict__ B,
    float* __restrict__ C, int M, int N, int K)
{
    constexpr int NT   = TN_ * 2;
    constexpr int SKB_ = TN_ + 8;
    constexpr uint32_t OFF_B = 10240;                  // A: 128 rows x 80B
    constexpr uint32_t STG   = 10240u + 32u * SKB_ * 2u;
    constexpr int BGRAN = 32 * (TN_ / 8);

    const int tid  = threadIdx.x;
    const int wid  = tid >> 5;
    const int lane = tid & 31;
    const int m0 = blockIdx.y * 128;
    const int n0 = blockIdx.x * TN_;

    const int wm = (wid & 1) * 64;
    const int wn = (wid >> 1) * 32;

    const uint32_t sb = smem_u32(dsm);

    float acc[4][4][4];
    #pragma unroll
    for (int i = 0; i < 4; i++)
        #pragma unroll
        for (int j = 0; j < 4; j++)
            #pragma unroll
            for (int k = 0; k < 4; k++) acc[i][j][k] = 0.0f;

    const int nk = K / 32;

    auto issue = [&](int slot, int kc) {
        const uint32_t s = sb + (uint32_t)slot * STG;
        #pragma unroll 2
        for (int i = tid; i < 512; i += NT) {
            int r = i >> 2, c = i & 3;
            uint32_t off = (uint32_t)(r * 80 + c * 16);
            size_t g = (size_t)(m0 + r) * K + (size_t)kc * 32 + c * 8;
            cp16(s + off, A + g);
        }
        #pragma unroll 2
        for (int i = tid; i < BGRAN; i += NT) {
            int r = i / (TN_ / 8), c = i % (TN_ / 8);
            uint32_t off = (uint32_t)(r * (SKB_ * 2) + c * 16);
            size_t g = (size_t)(kc * 32 + r) * N + n0 + c * 8;
            cp16(s + OFF_B + off, B + g);
        }
    };

    issue(0, 0);
    asm volatile("cp.async.commit_group;");
    if (nk > 1) issue(1, 1);
    asm volatile("cp.async.commit_group;");

    const int lm_row = lane & 15;
    const int lm_kch = (lane >> 4) * 8;

    int slot = 0;
    for (int kt = 0; kt < nk; kt++) {
        if (kt + 2 < nk) {
            int ps = slot + 2; if (ps >= 3) ps -= 3;
            issue(ps, kt + 2);
        }
        asm volatile("cp.async.commit_group;");
        asm volatile("cp.async.wait_group 2;");
        __syncthreads();

        const uint32_t stg = sb + (uint32_t)slot * STG;

        #pragma unroll
        for (int ks = 0; ks < 2; ks++) {
            const int k0 = ks * 16;
            uint32_t ah[4][4], bb[2][4];
            #pragma unroll
            for (int mi = 0; mi < 4; mi++) {
                uint32_t off = (uint32_t)((wm + mi * 16 + lm_row) * 80
                                          + (k0 + lm_kch) * 2);
                ldsm_x4(ah[mi], stg + off);
            }
            #pragma unroll
            for (int np = 0; np < 2; np++) {
                uint32_t off = (uint32_t)((k0 + lm_row) * (SKB_ * 2)
                                          + (wn + np * 16 + lm_kch) * 2);
                ldsm_x4_t(bb[np], stg + OFF_B + off);
            }
            #pragma unroll
            for (int mi = 0; mi < 4; mi++) {
                #pragma unroll
                for (int nj = 0; nj < 4; nj++) {
                    const uint32_t* bp = &bb[nj >> 1][(nj & 1) * 2];
                    mma_fp16(acc[mi][nj], ah[mi], bp);
                }
            }
        }
        __syncthreads();
        slot++; if (slot >= 3) slot = 0;
    }

    const int er = lane >> 2;
    const int ec = (lane & 3) * 2;
    #pragma unroll
    for (int mi = 0; mi < 4; mi++) {
        #pragma unroll
        for (int nj = 0; nj < 4; nj++) {
            const int row = m0 + wm + mi * 16 + er;
            const int col = n0 + wn + nj * 8 + ec;
            float2 v01; v01.x = acc[mi][nj][0]; v01.y = acc[mi][nj][1];
            float2 v23; v23.x = acc[mi][nj][2]; v23.y = acc[mi][nj][3];
            *(float2*)&C[(size_t)row * N + col]       = v01;
            *(float2*)&C[(size_t)(row + 8) * N + col] = v23;
        }
    }
}

#define SMEM_T64 (3 * (10240 + 32 * 72 * 2))    // 44544
#define SMEM_T96 (3 * (10240 + 32 * 104 * 2))   // 50688

// ---------------------------------------------------------------------------
// RoPE + compact fp16 emission: q roped+scaled -> qb; k roped -> kb; v -> vb.
// Reads fp32 qkv; writes ONLY fp16 buffers (qkv no longer read downstream).
// ---------------------------------------------------------------------------
__global__ void rope_kv_kernel(const float* __restrict__ qkv,
                               __half* __restrict__ qb,
                               __half* __restrict__ kb,
                               __half* __restrict__ vb, int n)
{
    int idx = blockIdx.x * blockDim.x + threadIdx.x;
    const int nrope = n * (NHEADS + NKV) * 32;

    if (idx < nrope) {
        int j   = idx & 31;
        int h   = (idx >> 5) % (NHEADS + NKV);
        int tok = idx / ((NHEADS + NKV) * 32);

        float2 cs = *(const float2*)&g_cs[(tok * 32 + j) * 2];

        if (h < NHEADS) {
            const float* base = qkv + (size_t)tok * QKVW + h * DHEAD;
            float x1 = base[j];
            float x2 = base[j + 32];
            __half* qo = qb + (size_t)tok * AOW + h * DHEAD;
            qo[j]      = __float2half((x1 * cs.x - x2 * cs.y) * 0.125f);
            qo[j + 32] = __float2half((x2 * cs.x + x1 * cs.y) * 0.125f);
        } else {
            int kh = h - NHEADS;
            const float* base = qkv + (size_t)tok * QKVW + NHEADS * DHEAD
                              + (size_t)kh * DHEAD;
            float x1 = base[j];
            float x2 = base[j + 32];
            __half* ko = kb + ((size_t)tok * NKV + kh) * DHEAD;
            ko[j]      = __float2half(x1 * cs.x - x2 * cs.y);
            ko[j + 32] = __float2half(x2 * cs.x + x1 * cs.y);
        }
        return;
    }

    int iv = idx - nrope;                       // v half2 pairs
    int totv = n * NKV * DHEAD / 2;             // n*256
    if (iv >= totv) return;
    int tok = iv >> 8;
    int r   = (iv & 255) * 2;
    const float* src = qkv + (size_t)tok * QKVW + (NHEADS + NKV) * DHEAD + r;
    __half2 hv = __halves2half2(__float2half(src[0]), __float2half(src[1]));
    *(__half2*)&vb[(size_t)tok * (NKV * DHEAD) + r] = hv;
}

// ---------------------------------------------------------------------------
// HMMA sliding-window attention with sinks, 4 tokens per block, fp16 inputs.
// Grid: (n/4, NKV). Block: 256 threads (8 warps).
//   p = j*8 + g  (j = token in block 0..3, g = head-in-group 0..7), 32 total.
//   Score:  S[144][32] = Kh[144][64] @ Qd^T   (HMMA)
//   Softmax over window (u = j..j+127) with sinks -> Ps[32][144] fp16 probs
//   PV:     O[32][64]  = Ps[32][144] @ Vh[144][64]
// K/V smem fills are raw cp.async 16B copies from the compact fp16 buffers
// (which fit in L2 entirely). Pad rows 131..143 zeroed with stores.
// ---------------------------------------------------------------------------
#define UNI 131
#define ATTN_SMEM 56448

__global__ __launch_bounds__(256) void attn_kernel(
    const __half* __restrict__ qb, const __half* __restrict__ kb,
    const __half* __restrict__ vb, const float* __restrict__ sinks,
    __half* __restrict__ out16, int n)
{
    __half* Kh  = (__half*)dsm;               // [144][72]
    float*  S   = (float*)dsm;                // [144][36] (aliases Kh)
    __half* Qd  = (__half*)(dsm + 20736);     // [64][40]
    __half* Ps  = (__half*)(dsm + 25856);     // [32][152]
    __half* Vh  = (__half*)(dsm + 35584);     // [144][72]
    float*  dinv = (float*)(dsm + 56320);     // [32]

    const int tok0 = blockIdx.x * 4;
    const int kv   = blockIdx.y;
    const int tid  = threadIdx.x;
    const int lane = tid & 31;
    const int wid  = tid >> 5;

    const int p0 = g_positions[tok0];

    const uint32_t khb = smem_u32(Kh);
    const uint32_t vhb = smem_u32(Vh);

    // --- K/V window fill via cp.async (131 rows x 8 granules each) ---
    for (int i = tid; i < UNI * 8; i += 256) {
        int u  = i >> 3;
        int c8 = (i & 7) << 3;
        int t = p0 - (WIN - 1) + u;
        t = max(0, min(t, n - 1));
        size_t src = ((size_t)t * NKV + kv) * DHEAD + c8;
        uint32_t off = (uint32_t)(u * 72 + c8) * 2;
        cp16(khb + off, kb + src);
        cp16(vhb + off, vb + src);
    }
    asm volatile("cp.async.commit_group;");

    // --- Q transpose copy [d][p], fp16 ---
    for (int i = tid; i < 32 * 64; i += 256) {
        int p = i & 31, d = i >> 5;
        Qd[d * 40 + p] = qb[(size_t)(tok0 + (p >> 3)) * AOW
                            + ((size_t)kv * 8 + (p & 7)) * DHEAD + d];
    }

    // --- zero pad rows 131..143 of Kh, Vh ---
    {
        uint4 z; z.x = 0; z.y = 0; z.z = 0; z.w = 0;
        for (int i = tid; i < 13 * 8; i += 256) {
            int u  = UNI + (i >> 3);
            int c8 = (i & 7) << 3;
            *(uint4*)&Kh[u * 72 + c8] = z;
            *(uint4*)&Vh[u * 72 + c8] = z;
        }
    }

    asm volatile("cp.async.wait_group 0;");
    __syncthreads();

    const int lm_row = lane & 15;
    const int lm_kch = (lane >> 4) * 8;
    const int er = lane >> 2;
    const int ec = (lane & 3) * 2;

    const uint32_t qdb = smem_u32(Qd);

    // --- score MMAs: warp w handles m-tile w; warp 0 also m-tile 8 ---
    float sacc[2][4][4];
    #pragma unroll
    for (int z = 0; z < 2; z++)
        #pragma unroll
        for (int nj = 0; nj < 4; nj++)
            #pragma unroll
            for (int q = 0; q < 4; q++) sacc[z][nj][q] = 0.0f;

    const int nmt = (wid == 0) ? 2 : 1;
    for (int z = 0; z < nmt; z++) {
        const int mt = (z == 0) ? wid : 8;
        #pragma unroll
        for (int kk = 0; kk < 4; kk++) {
            uint32_t a[4], bb[2][4];
            ldsm_x4(a, khb + (uint32_t)((mt * 16 + lm_row) * 72
                                        + kk * 16 + lm_kch) * 2);
            #pragma unroll
            for (int np = 0; np < 2; np++)
                ldsm_x4_t(bb[np], qdb + (uint32_t)((kk * 16 + lm_row) * 40
                                                   + np * 16 + lm_kch) * 2);
            #pragma unroll
            for (int nj = 0; nj < 4; nj++)
                mma_fp16(sacc[z][nj], a, &bb[nj >> 1][(nj & 1) * 2]);
        }
    }
    __syncthreads();   // all warps done reading Kh before S overwrites it

    // --- store S fragments; zero Ps ---
    for (int z = 0; z < nmt; z++) {
        const int mt = (z == 0) ? wid : 8;
        #pragma unroll
        for (int nj = 0; nj < 4; nj++) {
            int u0 = mt * 16 + er;
            int c  = nj * 8 + ec;
            float2 v01; v01.x = sacc[z][nj][0]; v01.y = sacc[z][nj][1];
            float2 v23; v23.x = sacc[z][nj][2]; v23.y = sacc[z][nj][3];
            *(float2*)&S[u0 * 36 + c]       = v01;
            *(float2*)&S[(u0 + 8) * 36 + c] = v23;
        }
    }
    for (int i = tid; i < 32 * 152 / 2; i += 256)
        ((uint32_t*)Ps)[i] = 0;
    __syncthreads();

    // --- softmax with sinks: warp wid handles pairs p = 4*wid .. 4*wid+3 ---
    #pragma unroll
    for (int pp = 0; pp < 4; pp++) {
        int p = (wid << 2) + pp;
        int j = p >> 3, g = p & 7;
        float vals[4];
        #pragma unroll
        for (int i = 0; i < 4; i++) {
            int u = j + lane + i * 32;
            bool tvalid = (p0 - (WIN - 1) + u) >= 0;
            vals[i] = tvalid ? S[u * 36 + p] : -INFINITY;
        }
        float m = fmaxf(fmaxf(vals[0], vals[1]), fmaxf(vals[2], vals[3]));
        #pragma unroll
        for (int off = 16; off; off >>= 1)
            m = fmaxf(m, __shfl_xor_sync(0xffffffffu, m, off));
        float snk = sinks[kv * GRP + g];
        m = fmaxf(m, snk);
        float ssum = 0.0f;
        #pragma unroll
        for (int i = 0; i < 4; i++) {
            int u = j + lane + i * 32;
            float pv = expf(vals[i] - m);
            Ps[p * 152 + u] = __float2half(pv);
            ssum += pv;
        }
        #pragma unroll
        for (int off = 16; off; off >>= 1)
            ssum += __shfl_xor_sync(0xffffffffu, ssum, off);
        if (lane == 0)
            dinv[p] = 1.0f / (ssum + expf(snk - m));
    }
    __syncthreads();

    // --- PV MMAs: warp w -> m-tile (w&1), d cols (w>>1)*16 .. +15 ---
    const uint32_t psb = smem_u32(Ps);
    const int mi = wid & 1;
    const int wn = (wid >> 1) * 16;

    float oacc[2][4];
    #pragma unroll
    for (int nj = 0; nj < 2; nj++)
        #pragma unroll
        for (int q = 0; q < 4; q++) oacc[nj][q] = 0.0f;

    #pragma unroll
    for (int kk = 0; kk < 9; kk++) {
        uint32_t a[4], bb[4];
        ldsm_x4(a, psb + (uint32_t)((mi * 16 + lm_row) * 152
                                    + kk * 16 + lm_kch) * 2);
        ldsm_x4_t(bb, vhb + (uint32_t)((kk * 16 + lm_row) * 72
                                       + wn + lm_kch) * 2);
        mma_fp16(oacc[0], a, &bb[0]);
        mma_fp16(oacc[1], a, &bb[2]);
    }

    // --- epilogue: scale by dinv, write fp16 output ---
    {
        const int pr0 = mi * 16 + er;
        const int pr1 = pr0 + 8;
        const float di0 = dinv[pr0];
        const float di1 = dinv[pr1];
        #pragma unroll
        for (int nj = 0; nj < 2; nj++) {
            const int d = wn + nj * 8 + ec;
            size_t o0 = (size_t)(tok0 + (pr0 >> 3)) * AOW
                      + ((size_t)kv * 8 + (pr0 & 7)) * DHEAD + d;
            size_t o1 = (size_t)(tok0 + (pr1 >> 3)) * AOW
                      + ((size_t)kv * 8 + (pr1 & 7)) * DHEAD + d;
            *(__half2*)&out16[o0] =
                __halves2half2(__float2half(oacc[nj][0] * di0),
                               __float2half(oacc[nj][1] * di0));
            *(__half2*)&out16[o1] =
                __halves2half2(__float2half(oacc[nj][2] * di1),
                               __float2half(oacc[nj][3] * di1));
        }
    }
}

// ---------------------------------------------------------------------------
extern "C" void kernel_launch(void* const* d_in, const int* in_sizes, int n_in,
                              void* d_out, int out_size)
{
    const float* hs    = (const float*)d_in[0];
    const float* wqkv  = (const float*)d_in[1];
    const float* wo    = (const float*)d_in[2];
    const float* sinks = (const float*)d_in[3];
    const void*  pos   = (const void*)d_in[4];
    float*       out   = (float*)d_out;

    const int n = in_sizes[0] / HDIM;   // 1024

    float* qkv_ptr;
    __half *ah, *ath, *wq, *wo16, *qb, *kb, *vb;
    cudaGetSymbolAddress((void**)&qkv_ptr, g_qkv);
    cudaGetSymbolAddress((void**)&ah,   g_ah);
    cudaGetSymbolAddress((void**)&ath,  g_ath);
    cudaGetSymbolAddress((void**)&wq,   g_wq);
    cudaGetSymbolAddress((void**)&wo16, g_wo);
    cudaGetSymbolAddress((void**)&qb,   g_qb);
    cudaGetSymbolAddress((void**)&kb,   g_kb);
    cudaGetSymbolAddress((void**)&vb,   g_vb);

    cudaFuncSetAttribute(gemm1p_kernel<64>,
                         cudaFuncAttributeMaxDynamicSharedMemorySize, SMEM_T64);
    cudaFuncSetAttribute(gemm1p_kernel<96>,
                         cudaFuncAttributeMaxDynamicSharedMemorySize, SMEM_T96);
    cudaFuncSetAttribute(attn_kernel,
                         cudaFuncAttributeMaxDynamicSharedMemorySize, ATTN_SMEM);

    // 0) positions + RoPE cos/sin table
    {
        int tot = n * 32;
        pos_table_kernel<<<(tot + 255) / 256, 256>>>(pos, n);
    }

    // 1) fused fp16 conversions
    {
        int n4_hs = (n * HDIM) / 4;
        int n4_wq = (HDIM * QKVW) / 4;
        int n4_wo = (AOW * HDIM) / 4;
        int tot = n4_hs + n4_wq + n4_wo;
        int stride = (tot + 3) / 4;
        cvt_all_kernel<<<(stride + 255) / 256, 256>>>(
            hs, wqkv, wo, ah, wq, wo16, n4_hs, n4_wq, n4_wo, stride);
    }

    // 2) qkv = hs @ Wqkv   (fp16 1-pass, N tile 64)
    {
        dim3 grid(QKVW / 64, n / 128);
        gemm1p_kernel<64><<<grid, 128, SMEM_T64>>>(ah, wq, qkv_ptr,
                                                   n, QKVW, HDIM);
    }

    // 3) RoPE -> compact fp16 Q/K/V buffers
    {
        int total = n * (NHEADS + NKV) * 32 + n * NKV * DHEAD / 2;
        rope_kv_kernel<<<(total + 255) / 256, 256>>>(qkv_ptr, qb, kb, vb, n);
    }

    // 4) HMMA attention (4 tokens/block), fp16 in/out
    {
        dim3 grid(n / 4, NKV);
        attn_kernel<<<grid, 256, ATTN_SMEM>>>(qb, kb, vb, sinks, ath, n);
    }

    // 5) out = attn @ Wo   (fp16 1-pass, N tile 96, single wave)
    {
        dim3 grid(HDIM / 96, n / 128);
        gemm1p_kernel<96><<<grid, 192, SMEM_T96>>>(ath, wo16, out,
                                                   n, HDIM, AOW);
    }
}